// round 1
// baseline (speedup 1.0000x reference)
#include <cuda_runtime.h>
#include <cstdint>

// BinaryTree hierarchical-softmax style forward:
//   z = W[leaf(input)]  (128-d)
//   path = 21 root-to-leaf nodes of context vertex
//   out[b] = prod_i sigmoid( dot(W[path_i], z) )
//
// d_in[0]: collocation int32 [65536, 2]
// d_in[1]: W float32 [2097151, 128]
// d_out  : float32 [65536]

#define DEPTH   20
#define NPATH   (DEPTH + 1)          // 21
#define OFFSET  ((1u << DEPTH) - 1u) // 1048575
#define NDIM    128
#define BATCH   65536

__global__ __launch_bounds__(256, 8)
void BinaryTree_65927747993695_kernel(const int* __restrict__ coll,
                                      const float* __restrict__ W,
                                      float* __restrict__ out)
{
    const int warp = (blockIdx.x * blockDim.x + threadIdx.x) >> 5;
    const int lane = threadIdx.x & 31;
    if (warp >= BATCH) return;

    // Broadcast-friendly loads (all lanes same address -> 1 wavefront each)
    const int v_in  = __ldg(&coll[2 * warp + 0]);
    const int v_ctx = __ldg(&coll[2 * warp + 1]);

    // z = W[leaf of input vertex], each lane holds 4 contiguous floats
    const size_t leaf_row = (size_t)(v_in + (int)OFFSET);
    const float4 z = __ldg(((const float4*)(W + leaf_row * NDIM)) + lane);

    // 1-based leaf id of context vertex; node at level i is (b >> (DEPTH-i)) - 1
    const unsigned b = (unsigned)v_ctx + OFFSET + 1u;

    // Fully unrolled: 21 independent LDG.128 in flight (MLP ~21)
    float partial[NPATH];
#pragma unroll
    for (int i = 0; i <= DEPTH; ++i) {
        const unsigned node = (b >> (DEPTH - i)) - 1u;
        const float4 w = __ldg(((const float4*)(W + (size_t)node * NDIM)) + lane);
        partial[i] = w.x * z.x + w.y * z.y + w.z * z.z + w.w * z.w;
    }

    // 21 butterfly reductions + sigmoid product
    float prob = 1.0f;
#pragma unroll
    for (int i = 0; i <= DEPTH; ++i) {
        float s = partial[i];
#pragma unroll
        for (int o = 16; o > 0; o >>= 1)
            s += __shfl_xor_sync(0xFFFFFFFFu, s, o);
        prob *= 1.0f / (1.0f + __expf(-s));
    }

    if (lane == 0) out[warp] = prob;
}

extern "C" void kernel_launch(void* const* d_in, const int* in_sizes, int n_in,
                              void* d_out, int out_size)
{
    const int*   coll = (const int*)d_in[0];
    const float* W    = (const float*)d_in[1];
    float*       out  = (float*)d_out;

    // 1 warp per batch element, 8 warps per block
    const int threads = 256;
    const int blocks  = (BATCH * 32) / threads;   // 8192
    BinaryTree_65927747993695_kernel<<<blocks, threads>>>(coll, W, out);
}

// round 2
// speedup vs baseline: 1.4197x; 1.4197x over previous
#include <cuda_runtime.h>
#include <cstdint>

// BinaryTree hierarchical-softmax forward:
//   z = W[leaf(input)]  (128-d)
//   path = 21 root-to-leaf nodes of context vertex
//   out[b] = prod_i sigmoid( dot(W[path_i], z) ) = 1 / prod_i (1 + exp(-s_i))
//
// d_in[0]: collocation int32 [65536, 2]
// d_in[1]: W float32 [2097151, 128]
// d_out  : float32 [65536]
//
// Layout: 4 batch elements per warp, 8 lanes per element.
// Each lane owns 64B (4 x float4) of every 512B row -> every LDG.128
// warp-instruction covers 4 complete 128B cache lines (perfect coalescing).
// Per-level reduction: 3-stage butterfly within the 8-lane group; sigmoid
// product is accumulated as a denominator product (1 MUFU.EX2 per level,
// single reciprocal at the end), SIMT-amortized across the 4 elements.

#define DEPTH   20
#define OFFSET  1048575              // (1<<DEPTH)-1
#define NDIM    128
#define BATCH   65536

__global__ __launch_bounds__(128, 8)
void BinaryTree_65927747993695_kernel(const int* __restrict__ coll,
                                      const float* __restrict__ W,
                                      float* __restrict__ out)
{
    const int warp = (blockIdx.x * blockDim.x + threadIdx.x) >> 5;
    const int lane = threadIdx.x & 31;
    const int sub  = lane >> 3;          // element-in-warp: 0..3
    const int l8   = lane & 7;           // lane-in-group:   0..7
    const int elem = warp * 4 + sub;
    if (elem >= BATCH) return;

    // Both vertices in one 8B load; broadcast within each 8-lane group.
    const int2 cv = __ldg((const int2*)coll + elem);

    // z = W[leaf of input vertex]; each lane holds 16 floats (4 x float4).
    const float4* zp = (const float4*)(W + (size_t)(cv.x + OFFSET) * NDIM);
    const float4 z0 = __ldg(zp + l8);
    const float4 z1 = __ldg(zp + l8 + 8);
    const float4 z2 = __ldg(zp + l8 + 16);
    const float4 z3 = __ldg(zp + l8 + 24);

    // 1-based leaf id of context vertex; node at level i = (b >> (DEPTH-i)) - 1
    const unsigned b = (unsigned)cv.y + (unsigned)OFFSET + 1u;

    float denom = 1.0f;
#pragma unroll
    for (int i = 0; i <= DEPTH; ++i) {
        const unsigned node = (b >> (DEPTH - i)) - 1u;
        const float4* wp = (const float4*)(W + (size_t)node * NDIM);
        const float4 w0 = __ldg(wp + l8);
        const float4 w1 = __ldg(wp + l8 + 8);
        const float4 w2 = __ldg(wp + l8 + 16);
        const float4 w3 = __ldg(wp + l8 + 24);

        float s = w0.x * z0.x + w0.y * z0.y + w0.z * z0.z + w0.w * z0.w
                + w1.x * z1.x + w1.y * z1.y + w1.z * z1.z + w1.w * z1.w
                + w2.x * z2.x + w2.y * z2.y + w2.z * z2.z + w2.w * z2.w
                + w3.x * z3.x + w3.y * z3.y + w3.z * z3.z + w3.w * z3.w;

        // 8-lane butterfly (xor 4,2,1 stays within the group)
        s += __shfl_xor_sync(0xFFFFFFFFu, s, 4);
        s += __shfl_xor_sync(0xFFFFFFFFu, s, 2);
        s += __shfl_xor_sync(0xFFFFFFFFu, s, 1);

        denom *= 1.0f + __expf(-s);      // FMUL + MUFU.EX2 (+FADD,FMUL)
    }

    if (l8 == 0) out[elem] = __fdividef(1.0f, denom);
}

extern "C" void kernel_launch(void* const* d_in, const int* in_sizes, int n_in,
                              void* d_out, int out_size)
{
    const int*   coll = (const int*)d_in[0];
    const float* W    = (const float*)d_in[1];
    float*       out  = (float*)d_out;

    // 4 elements per warp, 4 warps per block -> 16 elements per block
    const int threads = 128;
    const int blocks  = BATCH / 16;      // 4096
    BinaryTree_65927747993695_kernel<<<blocks, threads>>>(coll, W, out);
}

// round 3
// speedup vs baseline: 1.4957x; 1.0536x over previous
#include <cuda_runtime.h>
#include <cstdint>

// BinaryTree hierarchical-softmax forward:
//   z = W[leaf(input)], path = 21 root-to-leaf nodes of context vertex
//   out[b] = prod_i sigmoid(dot(W[path_i], z)) = 1 / prod_i (1 + exp(-s_i))
//
// d_in[0]: collocation int32 [65536, 2]
// d_in[1]: W float32 [2097151, 128]
// d_out  : float32 [65536]
//
// One warp per element. Each lane owns one float4 (16B) slice of every row,
// so each LDG.128 is one full coalesced 512B row. All 22 row loads are issued
// as one independent burst (MLP ~22) before any math. The 21 per-lane partial
// dot products are reduced across the warp with a compaction transpose-reduce
// (31 shuffles total, S[l] lands in lane l), then a single SIMT EX2 computes
// all 21 sigmoid denominators at once, and a 5-shuffle product finishes.

#define DEPTH   20
#define NPATH   21
#define OFFSET  1048575u             // (1<<DEPTH)-1
#define NDIM    128
#define BATCH   65536

__global__ __launch_bounds__(128, 4)
void BinaryTree_65927747993695_kernel(const int* __restrict__ coll,
                                      const float* __restrict__ W,
                                      float* __restrict__ out)
{
    const int warp = (blockIdx.x * blockDim.x + threadIdx.x) >> 5;
    const int lane = threadIdx.x & 31;
    if (warp >= BATCH) return;

    const int2 cv = __ldg((const int2*)coll + warp);

    // z row: lane's float4 slice
    const float4 z = __ldg((const float4*)(W + (size_t)((unsigned)cv.x + OFFSET) * NDIM) + lane);

    // 1-based leaf id; node at level i = (b >> (DEPTH-i)) - 1
    const unsigned b = (unsigned)cv.y + OFFSET + 1u;

    // ---- Load phase: 21 independent LDG.128 (plus z above) ----
    float4 w[NPATH];
#pragma unroll
    for (int i = 0; i < NPATH; ++i) {
        const unsigned node = (b >> (DEPTH - i)) - 1u;
        w[i] = __ldg((const float4*)(W + (size_t)node * NDIM) + lane);
    }

    // ---- Per-lane partial dot products (frees w regs) ----
    float a[32];
#pragma unroll
    for (int i = 0; i < NPATH; ++i)
        a[i] = w[i].x * z.x + w[i].y * z.y + w[i].z * z.z + w[i].w * z.w;
#pragma unroll
    for (int i = NPATH; i < 32; ++i)
        a[i] = 0.0f;

    // ---- Compaction transpose-reduce: 31 shuffles, a[0] in lane l == S[l] ----
#pragma unroll
    for (int m = 1; m < 32; m <<= 1) {
        const bool hi = (lane & m) != 0;
#pragma unroll
        for (int k = 0; k < 32; k += 2 * m) {
            const float send = hi ? a[k] : a[k + m];
            const float recv = __shfl_xor_sync(0xFFFFFFFFu, send, m);
            a[k] = (hi ? a[k + m] : a[k]) + recv;
        }
    }

    // Lane l (l < 21) now holds s_l. One SIMT EX2 covers all 21 levels.
    float c = (lane < NPATH) ? (1.0f + __expf(-a[0])) : 1.0f;

    // 5-shuffle product reduction
#pragma unroll
    for (int o = 16; o > 0; o >>= 1)
        c *= __shfl_xor_sync(0xFFFFFFFFu, c, o);

    if (lane == 0) out[warp] = __fdividef(1.0f, c);
}

extern "C" void kernel_launch(void* const* d_in, const int* in_sizes, int n_in,
                              void* d_out, int out_size)
{
    const int*   coll = (const int*)d_in[0];
    const float* W    = (const float*)d_in[1];
    float*       out  = (float*)d_out;

    // 1 warp per element, 4 warps per block
    const int threads = 128;
    const int blocks  = BATCH / 4;       // 16384
    BinaryTree_65927747993695_kernel<<<blocks, threads>>>(coll, W, out);
}

// round 4
// speedup vs baseline: 1.9806x; 1.3242x over previous
#include <cuda_runtime.h>
#include <cstdint>

// BinaryTree hierarchical-softmax forward:
//   z = W[leaf(input)], path = 21 root-to-leaf nodes of context vertex
//   out[b] = prod_i sigmoid(dot(W[path_i], z)) = 1 / prod_i (1 + exp(-s_i))
//
// d_in[0]: collocation int32 [65536, 2]
// d_in[1]: W float32 [2097151, 128]
// d_out  : float32 [65536]
//
// Persistent warps, one element per warp-iteration, software-pipelined:
//   - coll indices prefetched 2 elements ahead (latency fully hidden)
//   - the 22-row LDG.128 burst for element e+stride is issued right after
//     element e's partial dots free the row registers, so the burst flies
//     while e's transpose-reduce / sigmoid / store executes.
// This keeps ~22 loads per warp in flight ~80% of the time instead of ~33%,
// raising sustained DRAM-level MLP past the BW*latency knee.

#define DEPTH   20
#define NPATH   21
#define OFFSET  1048575u             // (1<<DEPTH)-1
#define NDIM    128
#define BATCH   65536

__global__ __launch_bounds__(128)
void BinaryTree_65927747993695_kernel(const int* __restrict__ coll,
                                      const float* __restrict__ W,
                                      float* __restrict__ out)
{
    const int tid    = blockIdx.x * blockDim.x + threadIdx.x;
    const int gw     = tid >> 5;
    const int lane   = tid & 31;
    const int stride = (gridDim.x * blockDim.x) >> 5;

    int e = gw;
    if (e >= BATCH) return;

    // --- prologue: coll for e and e+stride, row burst for e ---
    int2 cv0 = __ldg((const int2*)coll + e);
    int  e1  = e + stride;
    int2 cv1 = make_int2(0, 0);
    if (e1 < BATCH) cv1 = __ldg((const int2*)coll + e1);

    float4 z, w[NPATH];
    {
        z = __ldg((const float4*)(W + (size_t)((unsigned)cv0.x + OFFSET) * NDIM) + lane);
        const unsigned b = (unsigned)cv0.y + OFFSET + 1u;
#pragma unroll
        for (int i = 0; i < NPATH; ++i) {
            const unsigned node = (b >> (DEPTH - i)) - 1u;
            w[i] = __ldg((const float4*)(W + (size_t)node * NDIM) + lane);
        }
    }

    for (;;) {
        // prefetch coll two elements ahead
        const int e2 = e1 + stride;
        int2 cv2 = make_int2(0, 0);
        if (e2 < BATCH) cv2 = __ldg((const int2*)coll + e2);

        // --- partial dot products for element e (frees w[], z) ---
        float a[32];
#pragma unroll
        for (int i = 0; i < NPATH; ++i)
            a[i] = w[i].x * z.x + w[i].y * z.y + w[i].z * z.z + w[i].w * z.w;
#pragma unroll
        for (int i = NPATH; i < 32; ++i)
            a[i] = 0.0f;

        // --- issue next element's 22-row burst into the freed registers ---
        const bool have_next = (e1 < BATCH);
        if (have_next) {
            z = __ldg((const float4*)(W + (size_t)((unsigned)cv1.x + OFFSET) * NDIM) + lane);
            const unsigned b = (unsigned)cv1.y + OFFSET + 1u;
#pragma unroll
            for (int i = 0; i < NPATH; ++i) {
                const unsigned node = (b >> (DEPTH - i)) - 1u;
                w[i] = __ldg((const float4*)(W + (size_t)node * NDIM) + lane);
            }
        }

        // --- compaction transpose-reduce for e (overlaps next loads) ---
        // 31 shuffles total; afterwards lane l holds S[l] in a[0].
#pragma unroll
        for (int m = 1; m < 32; m <<= 1) {
            const bool hi = (lane & m) != 0;
#pragma unroll
            for (int k = 0; k < 32; k += 2 * m) {
                const float send = hi ? a[k] : a[k + m];
                const float recv = __shfl_xor_sync(0xFFFFFFFFu, send, m);
                a[k] = (hi ? a[k + m] : a[k]) + recv;
            }
        }

        // one SIMT EX2 serves all 21 levels, then 5-shuffle product
        float c = (lane < NPATH) ? (1.0f + __expf(-a[0])) : 1.0f;
#pragma unroll
        for (int o = 16; o > 0; o >>= 1)
            c *= __shfl_xor_sync(0xFFFFFFFFu, c, o);

        if (lane == 0) out[e] = __fdividef(1.0f, c);

        if (!have_next) return;
        e   = e1;
        e1  = e2;
        cv1 = cv2;
    }
}

extern "C" void kernel_launch(void* const* d_in, const int* in_sizes, int n_in,
                              void* d_out, int out_size)
{
    const int*   coll = (const int*)d_in[0];
    const float* W    = (const float*)d_in[1];
    float*       out  = (float*)d_out;

    // ~one full wave of persistent blocks (4 warps each); grid-stride inside.
    const int threads = 128;
    const int blocks  = 592;             // 2368 warps, ~28 elements per warp
    BinaryTree_65927747993695_kernel<<<blocks, threads>>>(coll, W, out);
}